// round 11
// baseline (speedup 1.0000x reference)
#include <cuda_runtime.h>
#include <cuda_bf16.h>
#include <mma.h>
#include <math.h>
#include <stdint.h>

using namespace nvcuda;

// Problem constants
#define H        512
#define BATCH    128
#define ENC_LEN  100
#define TSTEPS   1024
#define STEP_ELEMS (BATCH * H)

// Persistent geometry: 64 CTAs, each owns JC=8 h-dims (x4 gates = NB=32 rows),
// full batch M=128, K=512 in 4 chunks of 128.
#define GRID     64
#define NTHREADS 256
#define JC       8
#define NB       32
#define KCHUNK   128
#define NKC      4

// SMEM element strides (padded; all %8==0 so wmma ldm constraints hold)
#define A_LD     136        // A tile leading dim (bf16 elems)
#define W_LD     520        // W tile leading dim (bf16 elems)
#define D_LD     40         // D scratch leading dim (f32 elems)

// SMEM byte offsets from 1KB-aligned base
#define W_HI_OFF   0                         // 32 x 520 bf16 = 33280
#define W_LO_OFF   33280
#define ABUF_HI(b) (66560 + (b) * 69632)     // 128 x 136 bf16 = 34816
#define ABUF_LO(b) (ABUF_HI(b) + 34816)
#define D_OFF      ABUF_HI(0)                // aliases buf0 (fenced; see sync notes)
#define BIAS_OFF   205824                    // 32 floats
#define SMEM_DYN   (205824 + 128 + 1024)     // + alignment slack

__device__ unsigned long long g_count;
__global__ void init_kernel() { g_count = 0ULL; }

__device__ __forceinline__ uint32_t bf16_rne_bits(float x) {
    uint32_t xb = __float_as_uint(x);
    return (xb + 0x7FFFu + ((xb >> 16) & 1u)) & 0xFFFF0000u;
}
// pack two fp32 into bf16x2 (e0 -> low half, e1 -> high half)
__device__ __forceinline__ uint32_t pack2_bf16(float e0, float e1) {
    uint32_t r;
    asm("cvt.rn.bf16x2.f32 %0, %1, %2;" : "=r"(r) : "f"(e1), "f"(e0));
    return r;
}
__device__ __forceinline__ float fsigm(float x) { return __fdividef(1.0f, 1.0f + __expf(-x)); }
__device__ __forceinline__ float ftanh(float x) { return __fdividef(2.0f, 1.0f + __expf(-2.0f * x)) - 1.0f; }

// ---------------------------------------------------------------------------
// Step 0 (exact fp32): x = 0, h = enc[0, b, ENC_LEN-1, :]
// ---------------------------------------------------------------------------
__global__ void gru_step0(const float* __restrict__ enc,
                          const float* __restrict__ W_hh,
                          const float* __restrict__ b_ih,
                          const float* __restrict__ b_hh,
                          float* __restrict__ out)
{
    __shared__ float h0s[H];
    __shared__ float gh[3 * H];

    const int b = blockIdx.x, tid = threadIdx.x;
    const float* src = enc + ((size_t)b * ENC_LEN + (ENC_LEN - 1)) * H;
    for (int i = tid; i < H; i += NTHREADS) h0s[i] = src[i];
    __syncthreads();

    const int warp = tid >> 5, lane = tid & 31;
    const float4* h4 = (const float4*)h0s;
    for (int row = warp; row < 3 * H; row += (NTHREADS / 32)) {
        const float4* wr = (const float4*)(W_hh + (size_t)row * H);
        float s = 0.0f;
        #pragma unroll 4
        for (int i = lane; i < H / 4; i += 32) {
            float4 w = wr[i]; float4 hv = h4[i];
            s = fmaf(w.x, hv.x, s); s = fmaf(w.y, hv.y, s);
            s = fmaf(w.z, hv.z, s); s = fmaf(w.w, hv.w, s);
        }
        #pragma unroll
        for (int o = 16; o > 0; o >>= 1) s += __shfl_xor_sync(0xffffffffu, s, o);
        if (lane == 0) gh[row] = s;
    }
    __syncthreads();

    for (int j = tid; j < H; j += NTHREADS) {
        float r = 1.0f / (1.0f + expf(-(b_ih[j] + gh[j] + b_hh[j])));
        float z = 1.0f / (1.0f + expf(-(b_ih[H + j] + gh[H + j] + b_hh[H + j])));
        float n = tanhf(b_ih[2*H + j] + r * (gh[2*H + j] + b_hh[2*H + j]));
        float ho = h0s[j];
        out[(size_t)b * H + j] = n + z * (ho - n);
    }
}

// ---------------------------------------------------------------------------
// Persistent wmma kernel: steps 1..1023.
// D[128, 32] = h[128, 512] x Wc[32, 512]^T via bf16 hi/lo 3-term wmma.
// Wc rows (n = gate*8 + jl): 0=r (Wih+Whh), 1=z (Wih+Whh), 2=a (Wih), 3=g (Whh).
//   h' = (1-z)*tanh(a + sig(r)*g) + z*h
// 8 warps x M=16 slice each; accumulators in registers across all K chunks.
// ---------------------------------------------------------------------------
__global__ void __launch_bounds__(NTHREADS, 1)
gru_persist(const float* __restrict__ W_ih,
            const float* __restrict__ W_hh,
            const float* __restrict__ b_ih,
            const float* __restrict__ b_hh,
            float* __restrict__ out)
{
    extern __shared__ char smem_raw[];
    char* smem = (char*)(((uintptr_t)smem_raw + 1023u) & ~(uintptr_t)1023u);

    const int tid = threadIdx.x;
    const int wid = tid >> 5;
    const int jc  = blockIdx.x;           // 0..63 j-chunk
    const int jglob = jc * JC;

    __nv_bfloat16* w_hi = (__nv_bfloat16*)(smem + W_HI_OFF);
    __nv_bfloat16* w_lo = (__nv_bfloat16*)(smem + W_LO_OFF);
    float* bias_s = (float*)(smem + BIAS_OFF);
    float* d_s    = (float*)(smem + D_OFF);

    // ---- Prologue: combined weights -> bf16 hi/lo SMEM tiles (once)
    for (int idx = tid; idx < NB * H; idx += NTHREADS) {
        int r = idx >> 9, k = idx & (H - 1);
        int g = r >> 3, jl = r & 7;
        int j = jglob + jl;
        float c;
        if (g == 0)      c = W_ih[(size_t)j * H + k]           + W_hh[(size_t)j * H + k];
        else if (g == 1) c = W_ih[(size_t)(H + j) * H + k]     + W_hh[(size_t)(H + j) * H + k];
        else if (g == 2) c = W_ih[(size_t)(2*H + j) * H + k];
        else             c = W_hh[(size_t)(2*H + j) * H + k];
        uint32_t hb = bf16_rne_bits(c);
        float lo = c - __uint_as_float(hb);
        w_hi[r * W_LD + k] = __ushort_as_bfloat16((unsigned short)(hb >> 16));
        w_lo[r * W_LD + k] = __float2bfloat16(lo);
    }
    if (tid < NB) {
        int g = tid >> 3, jl = tid & 7;
        int j = jglob + jl;
        float v;
        if (g == 0)      v = b_ih[j]        + b_hh[j];
        else if (g == 1) v = b_ih[H + j]    + b_hh[H + j];
        else if (g == 2) v = b_ih[2*H + j];
        else             v = b_hh[2*H + j];
        bias_s[tid] = v;
    }
    __syncthreads();

    const int m0 = wid * 16;                // this warp's batch slice

    // convert-loop index mapping (per chunk: 128x128 fp32 = 16 float4/thread)
    const int cm  = tid >> 5;               // base row (8 rows apart per i)
    const int ck4 = (tid & 31) << 2;        // k offset within chunk

    for (int t = 1; t < TSTEPS; ++t) {
        const float* hsrc = out + (size_t)(t - 1) * STEP_ELEMS;

        wmma::fragment<wmma::accumulator, 16, 16, 16, float> acc[2];
        wmma::fill_fragment(acc[0], 0.0f);
        wmma::fill_fragment(acc[1], 0.0f);

        // prefetch chunk 0
        float4 v[16];
        #pragma unroll
        for (int i = 0; i < 16; ++i)
            v[i] = __ldcg((const float4*)(hsrc + (size_t)(cm + i * 8) * H + ck4));

        #pragma unroll 1
        for (int kc = 0; kc < NKC; ++kc) {
            const int buf = kc & 1;
            __nv_bfloat16* ahi = (__nv_bfloat16*)(smem + ABUF_HI(buf));
            __nv_bfloat16* alo = (__nv_bfloat16*)(smem + ABUF_LO(buf));

            // ---- convert prefetched chunk -> bf16 hi/lo A tiles
            #pragma unroll
            for (int i = 0; i < 16; ++i) {
                float4 x = v[i];
                uint32_t r0 = bf16_rne_bits(x.x), r1 = bf16_rne_bits(x.y);
                uint32_t r2 = bf16_rne_bits(x.z), r3 = bf16_rne_bits(x.w);
                float l0 = x.x - __uint_as_float(r0);
                float l1 = x.y - __uint_as_float(r1);
                float l2 = x.z - __uint_as_float(r2);
                float l3 = x.w - __uint_as_float(r3);
                int m = cm + i * 8;
                uint32_t eoff = (uint32_t)m * A_LD + ck4;
                *(uint2*)((char*)ahi + eoff * 2) =
                    make_uint2(__byte_perm(r0, r1, 0x7632), __byte_perm(r2, r3, 0x7632));
                *(uint2*)((char*)alo + eoff * 2) =
                    make_uint2(pack2_bf16(l0, l1), pack2_bf16(l2, l3));
            }
            __syncthreads();

            // ---- prefetch next chunk while wmma runs
            if (kc + 1 < NKC) {
                const float* nsrc = hsrc + (kc + 1) * KCHUNK;
                #pragma unroll
                for (int i = 0; i < 16; ++i)
                    v[i] = __ldcg((const float4*)(nsrc + (size_t)(cm + i * 8) * H + ck4));
            }

            // ---- wmma compute: 8 k-steps x 2 n-tiles x 3 terms
            #pragma unroll 2
            for (int ks = 0; ks < KCHUNK / 16; ++ks) {
                wmma::fragment<wmma::matrix_a, 16, 16, 16, __nv_bfloat16, wmma::row_major> a_hi, a_lo;
                wmma::load_matrix_sync(a_hi, ahi + m0 * A_LD + ks * 16, A_LD);
                wmma::load_matrix_sync(a_lo, alo + m0 * A_LD + ks * 16, A_LD);
                const int kg = kc * KCHUNK + ks * 16;
                #pragma unroll
                for (int n = 0; n < 2; ++n) {
                    wmma::fragment<wmma::matrix_b, 16, 16, 16, __nv_bfloat16, wmma::col_major> b_hi, b_lo;
                    wmma::load_matrix_sync(b_hi, w_hi + n * 16 * W_LD + kg, W_LD);
                    wmma::load_matrix_sync(b_lo, w_lo + n * 16 * W_LD + kg, W_LD);
                    wmma::mma_sync(acc[n], a_hi, b_hi, acc[n]);
                    wmma::mma_sync(acc[n], a_lo, b_hi, acc[n]);
                    wmma::mma_sync(acc[n], a_hi, b_lo, acc[n]);
                }
            }
        }

        // ---- epilogue: D -> SMEM (aliases buf0; all warps past compute on buf0)
        __syncthreads();
        wmma::store_matrix_sync(d_s + m0 * D_LD + 0,  acc[0], D_LD, wmma::mem_row_major);
        wmma::store_matrix_sync(d_s + m0 * D_LD + 16, acc[1], D_LD, wmma::mem_row_major);
        __syncthreads();

        if (tid < BATCH) {
            const int b = tid;
            const float* drow = d_s + b * D_LD;
            const float* hop = hsrc + (size_t)b * H + jglob;
            float4 hoa = __ldcg((const float4*)hop);
            float4 hob = __ldcg((const float4*)(hop + 4));
            float ho[8] = { hoa.x, hoa.y, hoa.z, hoa.w, hob.x, hob.y, hob.z, hob.w };

            float res[8];
            #pragma unroll
            for (int jl = 0; jl < 8; ++jl) {
                float r = fsigm(drow[jl]      + bias_s[jl]);
                float z = fsigm(drow[8 + jl]  + bias_s[8 + jl]);
                float a = drow[16 + jl] + bias_s[16 + jl];
                float g = drow[24 + jl] + bias_s[24 + jl];
                float n = ftanh(a + r * g);
                res[jl] = n + z * (ho[jl] - n);
            }
            float* dst = out + (size_t)t * STEP_ELEMS + (size_t)b * H + jglob;
            __stcg((float4*)dst,       make_float4(res[0], res[1], res[2], res[3]));
            __stcg((float4*)(dst + 4), make_float4(res[4], res[5], res[6], res[7]));
        }

        // ---- grid barrier (skip after final step)
        if (t + 1 < TSTEPS) {
            __threadfence();
            __syncthreads();
            if (tid == 0) {
                atomicAdd(&g_count, 1ULL);
                unsigned long long target = (unsigned long long)t * (unsigned long long)GRID;
                while (*(volatile unsigned long long*)&g_count < target) { }
            }
            __syncthreads();
        } else {
            __syncthreads();   // uniform exit; d_s reads fenced before return
        }
    }
}

// ---------------------------------------------------------------------------
// Harness entry. Inputs: enc f32[1,128,100,512], W_ih f32[1536,512],
// W_hh f32[1536,512], b_ih f32[1536], b_hh f32[1536], out_len i32.
// Output: f32[1024*128, 1, 512]
// ---------------------------------------------------------------------------
extern "C" void kernel_launch(void* const* d_in, const int* in_sizes, int n_in,
                              void* d_out, int out_size)
{
    const float* enc  = (const float*)d_in[0];
    const float* W_ih = (const float*)d_in[1];
    const float* W_hh = (const float*)d_in[2];
    const float* b_ih = (const float*)d_in[3];
    const float* b_hh = (const float*)d_in[4];
    float* out = (float*)d_out;

    cudaFuncSetAttribute(gru_persist, cudaFuncAttributeMaxDynamicSharedMemorySize, SMEM_DYN);

    init_kernel<<<1, 1>>>();
    gru_step0<<<BATCH, NTHREADS>>>(enc, W_hh, b_ih, b_hh, out);
    gru_persist<<<GRID, NTHREADS, SMEM_DYN>>>(W_ih, W_hh, b_ih, b_hh, out);
}

// round 12
// speedup vs baseline: 1.6535x; 1.6535x over previous
#include <cuda_runtime.h>
#include <cuda_bf16.h>
#include <mma.h>
#include <math.h>
#include <stdint.h>

using namespace nvcuda;

// Problem constants
#define H        512
#define BATCH    128
#define ENC_LEN  100
#define TSTEPS   1024
#define STEP_ELEMS (BATCH * H)

// Persistent geometry: 128 CTAs = 64 j-chunks x 2 batch-halves.
// Each CTA: M=64 batch rows, N=32 weight rows (4 gates x JC=8), K=512 (4 chunks).
#define GRID     128
#define NTHREADS 256
#define JC       8
#define NB       32
#define MROWS    64
#define KCHUNK   128
#define NKC      4

// SMEM element strides (all %8==0 for wmma ldm)
#define A_LD     136        // A chunk tile leading dim (bf16)
#define W_LD     520        // W tile leading dim (bf16)
#define D_LD     40         // D scratch leading dim (f32)

// SMEM byte offsets
#define W_HI_OFF   0                          // 32 x 520 bf16 = 33280
#define W_LO_OFF   33280
#define ABUF_HI(b) (66560 + (b) * 34816)      // per buf: hi 64x136x2=17408 + lo
#define ABUF_LO(b) (ABUF_HI(b) + 17408)
#define D_OFF      ABUF_HI(0)                 // aliases buf0 (fenced)
#define BIAS_OFF   136192                     // 32 floats
#define SMEM_DYN   (136192 + 128 + 1024)

// Parity-double-buffered bf16 hi/lo image of h (written once per element per step)
__device__ __align__(16) __nv_bfloat16 g_hhi[2][STEP_ELEMS];
__device__ __align__(16) __nv_bfloat16 g_hlo[2][STEP_ELEMS];
__device__ unsigned long long g_count;

__global__ void init_kernel() { g_count = 0ULL; }

__device__ __forceinline__ uint32_t smem_u32(const void* p) {
    uint32_t a;
    asm("{ .reg .u64 t; cvta.to.shared.u64 t, %1; cvt.u32.u64 %0, t; }" : "=r"(a) : "l"(p));
    return a;
}
#define CP_ASYNC16(dst_u32, gptr) \
    asm volatile("cp.async.cg.shared.global [%0], [%1], 16;" :: "r"(dst_u32), "l"(gptr))
#define CP_COMMIT() asm volatile("cp.async.commit_group;" ::: "memory")
#define CP_WAIT(N)  asm volatile("cp.async.wait_group %0;" :: "n"(N) : "memory")

__device__ __forceinline__ uint32_t bf16_rne_bits(float x) {
    uint32_t xb = __float_as_uint(x);
    return (xb + 0x7FFFu + ((xb >> 16) & 1u)) & 0xFFFF0000u;
}
// pack two fp32 -> bf16x2 (e0 low, e1 high)
__device__ __forceinline__ uint32_t pack2_bf16(float e0, float e1) {
    uint32_t r;
    asm("cvt.rn.bf16x2.f32 %0, %1, %2;" : "=r"(r) : "f"(e1), "f"(e0));
    return r;
}
__device__ __forceinline__ void stg_cg_v4(void* p, uint32_t x, uint32_t y, uint32_t z, uint32_t w) {
    asm volatile("st.global.cg.v4.b32 [%0], {%1,%2,%3,%4};" :: "l"(p), "r"(x), "r"(y), "r"(z), "r"(w));
}
__device__ __forceinline__ float fsigm(float x) { return __fdividef(1.0f, 1.0f + __expf(-x)); }
__device__ __forceinline__ float ftanh(float x) { return __fdividef(2.0f, 1.0f + __expf(-2.0f * x)) - 1.0f; }

// ---------------------------------------------------------------------------
// Step 0 (exact fp32): x = 0, h = enc[0, b, ENC_LEN-1, :]. Also seeds the
// bf16 hi/lo scratch at parity 0.
// ---------------------------------------------------------------------------
__global__ void gru_step0(const float* __restrict__ enc,
                          const float* __restrict__ W_hh,
                          const float* __restrict__ b_ih,
                          const float* __restrict__ b_hh,
                          float* __restrict__ out)
{
    __shared__ float h0s[H];
    __shared__ float gh[3 * H];

    const int b = blockIdx.x, tid = threadIdx.x;
    const float* src = enc + ((size_t)b * ENC_LEN + (ENC_LEN - 1)) * H;
    for (int i = tid; i < H; i += NTHREADS) h0s[i] = src[i];
    __syncthreads();

    const int warp = tid >> 5, lane = tid & 31;
    const float4* h4 = (const float4*)h0s;
    for (int row = warp; row < 3 * H; row += (NTHREADS / 32)) {
        const float4* wr = (const float4*)(W_hh + (size_t)row * H);
        float s = 0.0f;
        #pragma unroll 4
        for (int i = lane; i < H / 4; i += 32) {
            float4 w = wr[i]; float4 hv = h4[i];
            s = fmaf(w.x, hv.x, s); s = fmaf(w.y, hv.y, s);
            s = fmaf(w.z, hv.z, s); s = fmaf(w.w, hv.w, s);
        }
        #pragma unroll
        for (int o = 16; o > 0; o >>= 1) s += __shfl_xor_sync(0xffffffffu, s, o);
        if (lane == 0) gh[row] = s;
    }
    __syncthreads();

    for (int j = tid; j < H; j += NTHREADS) {
        float r = 1.0f / (1.0f + expf(-(b_ih[j] + gh[j] + b_hh[j])));
        float z = 1.0f / (1.0f + expf(-(b_ih[H + j] + gh[H + j] + b_hh[H + j])));
        float n = tanhf(b_ih[2*H + j] + r * (gh[2*H + j] + b_hh[2*H + j]));
        float ho = h0s[j];
        float res = n + z * (ho - n);
        out[(size_t)b * H + j] = res;
        uint32_t hb = bf16_rne_bits(res);
        g_hhi[0][(size_t)b * H + j] = __ushort_as_bfloat16((unsigned short)(hb >> 16));
        g_hlo[0][(size_t)b * H + j] = __float2bfloat16(res - __uint_as_float(hb));
    }
}

// ---------------------------------------------------------------------------
// Persistent wmma kernel: steps 1..1023.
// D[64, 32] = h_half[64, 512] x Wc[32, 512]^T via bf16 hi/lo 3-term wmma.
// A tiles come pre-split from g_hhi/g_hlo via cp.async (no per-step convert).
// Wc rows (n = gate*8+jl): 0=r (Wih+Whh), 1=z (Wih+Whh), 2=a (Wih), 3=g (Whh).
//   h' = (1-z)*tanh(a + sig(r)*g) + z*h
// 8 warps = 4 m-slices x 2 n-tiles; accumulators in registers across K.
// ---------------------------------------------------------------------------
__global__ void __launch_bounds__(NTHREADS, 1)
gru_persist(const float* __restrict__ W_ih,
            const float* __restrict__ W_hh,
            const float* __restrict__ b_ih,
            const float* __restrict__ b_hh,
            float* __restrict__ out)
{
    extern __shared__ char smem_raw[];
    char* smem = (char*)(((uintptr_t)smem_raw + 1023u) & ~(uintptr_t)1023u);

    const int tid = threadIdx.x;
    const int wid = tid >> 5;
    const int jc     = blockIdx.x >> 1;        // 0..63
    const int mhalf  = blockIdx.x & 1;         // 0..1
    const int jglob  = jc * JC;
    const int mb0    = mhalf * MROWS;

    __nv_bfloat16* w_hi = (__nv_bfloat16*)(smem + W_HI_OFF);
    __nv_bfloat16* w_lo = (__nv_bfloat16*)(smem + W_LO_OFF);
    float* bias_s = (float*)(smem + BIAS_OFF);
    float* d_s    = (float*)(smem + D_OFF);

    // ---- Prologue: combined weights -> bf16 hi/lo SMEM tiles (once)
    for (int idx = tid; idx < NB * H; idx += NTHREADS) {
        int r = idx >> 9, k = idx & (H - 1);
        int g = r >> 3, jl = r & 7;
        int j = jglob + jl;
        float c;
        if (g == 0)      c = W_ih[(size_t)j * H + k]           + W_hh[(size_t)j * H + k];
        else if (g == 1) c = W_ih[(size_t)(H + j) * H + k]     + W_hh[(size_t)(H + j) * H + k];
        else if (g == 2) c = W_ih[(size_t)(2*H + j) * H + k];
        else             c = W_hh[(size_t)(2*H + j) * H + k];
        uint32_t hb = bf16_rne_bits(c);
        w_hi[r * W_LD + k] = __ushort_as_bfloat16((unsigned short)(hb >> 16));
        w_lo[r * W_LD + k] = __float2bfloat16(c - __uint_as_float(hb));
    }
    if (tid < NB) {
        int g = tid >> 3, jl = tid & 7;
        int j = jglob + jl;
        float v;
        if (g == 0)      v = b_ih[j]        + b_hh[j];
        else if (g == 1) v = b_ih[H + j]    + b_hh[H + j];
        else if (g == 2) v = b_ih[2*H + j];
        else             v = b_hh[2*H + j];
        bias_s[tid] = v;
    }
    __syncthreads();

    const int ms = wid >> 1;               // 0..3 m-slice (16 rows)
    const int nt = wid & 1;                // 0..1 n-tile
    const int m0 = ms * 16;
    const int n0 = nt * 16;

    // cp.async mapping: per chunk per term, 64 rows x 128 bf16 = 1024 x 16B units
    const int c_row = tid >> 2;                   // rows via unit>>4 pattern below
    (void)c_row;

    for (int t = 1; t < TSTEPS; ++t) {
        const int rpar = (t - 1) & 1;
        const int wpar = t & 1;
        const __nv_bfloat16* shi = g_hhi[rpar];
        const __nv_bfloat16* slo = g_hlo[rpar];

        wmma::fragment<wmma::accumulator, 16, 16, 16, float> acc;
        wmma::fill_fragment(acc, 0.0f);

        // issue chunk copies kc into buf kc&1 (hi + lo), one commit group each
        auto issue_chunk = [&](int kc) {
            char* ahi = smem + ABUF_HI(kc & 1);
            char* alo = smem + ABUF_LO(kc & 1);
            const __nv_bfloat16* ghi = shi + (size_t)mb0 * H + kc * KCHUNK;
            const __nv_bfloat16* glo = slo + (size_t)mb0 * H + kc * KCHUNK;
            #pragma unroll
            for (int i = 0; i < 4; ++i) {
                int unit = tid + i * NTHREADS;      // 0..1023
                int row  = unit >> 4;
                int u    = unit & 15;
                uint32_t doff = (uint32_t)row * (A_LD * 2) + u * 16;
                size_t   soff = (size_t)row * H + u * 8;
                CP_ASYNC16(smem_u32(ahi + doff), ghi + soff);
                CP_ASYNC16(smem_u32(alo + doff), glo + soff);
            }
            CP_COMMIT();
        };

        issue_chunk(0);
        issue_chunk(1);

        #pragma unroll 1
        for (int kc = 0; kc < NKC; ++kc) {
            if (kc == NKC - 1) { CP_WAIT(0); } else { CP_WAIT(1); }
            __syncthreads();

            __nv_bfloat16* ahi = (__nv_bfloat16*)(smem + ABUF_HI(kc & 1));
            __nv_bfloat16* alo = (__nv_bfloat16*)(smem + ABUF_LO(kc & 1));

            #pragma unroll 2
            for (int ks = 0; ks < KCHUNK / 16; ++ks) {
                wmma::fragment<wmma::matrix_a, 16, 16, 16, __nv_bfloat16, wmma::row_major> a_hi, a_lo;
                wmma::load_matrix_sync(a_hi, ahi + m0 * A_LD + ks * 16, A_LD);
                wmma::load_matrix_sync(a_lo, alo + m0 * A_LD + ks * 16, A_LD);
                const int kg = kc * KCHUNK + ks * 16;
                wmma::fragment<wmma::matrix_b, 16, 16, 16, __nv_bfloat16, wmma::col_major> b_hi, b_lo;
                wmma::load_matrix_sync(b_hi, w_hi + n0 * W_LD + kg, W_LD);
                wmma::load_matrix_sync(b_lo, w_lo + n0 * W_LD + kg, W_LD);
                wmma::mma_sync(acc, a_hi, b_hi, acc);
                wmma::mma_sync(acc, a_lo, b_hi, acc);
                wmma::mma_sync(acc, a_hi, b_lo, acc);
            }
            __syncthreads();
            if (kc + 2 < NKC) issue_chunk(kc + 2);
        }

        // ---- epilogue: D -> SMEM (aliases buf0; all cp.async retired)
        wmma::store_matrix_sync(d_s + m0 * D_LD + n0, acc, D_LD, wmma::mem_row_major);
        __syncthreads();

        if (tid < MROWS) {
            const int b = mb0 + tid;
            const float* drow = d_s + tid * D_LD;
            const float* hop = out + (size_t)(t - 1) * STEP_ELEMS + (size_t)b * H + jglob;
            float4 hoa = __ldcg((const float4*)hop);
            float4 hob = __ldcg((const float4*)(hop + 4));
            float ho[8] = { hoa.x, hoa.y, hoa.z, hoa.w, hob.x, hob.y, hob.z, hob.w };

            float res[8];
            uint32_t hi4[4], lo4[4];
            #pragma unroll
            for (int jl = 0; jl < 8; ++jl) {
                float r = fsigm(drow[jl]      + bias_s[jl]);
                float z = fsigm(drow[8 + jl]  + bias_s[8 + jl]);
                float a = drow[16 + jl] + bias_s[16 + jl];
                float g = drow[24 + jl] + bias_s[24 + jl];
                float n = ftanh(a + r * g);
                res[jl] = n + z * (ho[jl] - n);
            }
            #pragma unroll
            for (int p = 0; p < 4; ++p) {
                uint32_t h0b = bf16_rne_bits(res[2*p]);
                uint32_t h1b = bf16_rne_bits(res[2*p + 1]);
                hi4[p] = (h0b >> 16) | (h1b & 0xFFFF0000u);
                lo4[p] = pack2_bf16(res[2*p]     - __uint_as_float(h0b),
                                    res[2*p + 1] - __uint_as_float(h1b));
            }
            float* dst = out + (size_t)t * STEP_ELEMS + (size_t)b * H + jglob;
            __stcg((float4*)dst,       make_float4(res[0], res[1], res[2], res[3]));
            __stcg((float4*)(dst + 4), make_float4(res[4], res[5], res[6], res[7]));
            stg_cg_v4(&g_hhi[wpar][(size_t)b * H + jglob], hi4[0], hi4[1], hi4[2], hi4[3]);
            stg_cg_v4(&g_hlo[wpar][(size_t)b * H + jglob], lo4[0], lo4[1], lo4[2], lo4[3]);
        }

        // ---- grid barrier (skip after final step)
        if (t + 1 < TSTEPS) {
            __threadfence();
            __syncthreads();
            if (tid == 0) {
                atomicAdd(&g_count, 1ULL);
                unsigned long long target = (unsigned long long)t * (unsigned long long)GRID;
                while (*(volatile unsigned long long*)&g_count < target) { }
            }
            __syncthreads();
        } else {
            __syncthreads();
        }
    }
}

// ---------------------------------------------------------------------------
// Harness entry. Inputs: enc f32[1,128,100,512], W_ih f32[1536,512],
// W_hh f32[1536,512], b_ih f32[1536], b_hh f32[1536], out_len i32.
// Output: f32[1024*128, 1, 512]
// ---------------------------------------------------------------------------
extern "C" void kernel_launch(void* const* d_in, const int* in_sizes, int n_in,
                              void* d_out, int out_size)
{
    const float* enc  = (const float*)d_in[0];
    const float* W_ih = (const float*)d_in[1];
    const float* W_hh = (const float*)d_in[2];
    const float* b_ih = (const float*)d_in[3];
    const float* b_hh = (const float*)d_in[4];
    float* out = (float*)d_out;

    cudaFuncSetAttribute(gru_persist, cudaFuncAttributeMaxDynamicSharedMemorySize, SMEM_DYN);

    init_kernel<<<1, 1>>>();
    gru_step0<<<BATCH, NTHREADS>>>(enc, W_hh, b_ih, b_hh, out);
    gru_persist<<<GRID, NTHREADS, SMEM_DYN>>>(W_ih, W_hh, b_ih, b_hh, out);
}

// round 13
// speedup vs baseline: 2.0034x; 1.2116x over previous
#include <cuda_runtime.h>
#include <cuda_bf16.h>
#include <mma.h>
#include <math.h>
#include <stdint.h>

using namespace nvcuda;

// Problem constants
#define H        512
#define BATCH    128
#define ENC_LEN  100
#define TSTEPS   1024
#define STEP_ELEMS (BATCH * H)

// Persistent geometry: 128 CTAs = 64 j-chunks x 2 batch-halves.
// Each CTA: M=64 batch rows, N=32 weight rows (4 gates x JC=8), K=512 (4 chunks).
#define GRID     128
#define NTHREADS 256
#define JC       8
#define NB       32
#define MROWS    64
#define KCHUNK   128
#define NKC      4

// SMEM element strides (all %8==0 for wmma ldm)
#define A_LD     136        // A chunk tile leading dim (bf16)
#define W_LD     520        // W tile leading dim (bf16)
#define D_LD     40         // D scratch leading dim (f32)

// SMEM byte offsets — 4 A buffers (all chunks in flight)
#define W_HI_OFF   0                          // 32 x 520 bf16 = 33280
#define W_LO_OFF   33280
#define ABUF_HI(b) (66560 + (b) * 34816)      // per buf: hi 64x136x2=17408 + lo
#define ABUF_LO(b) (ABUF_HI(b) + 17408)
#define D_OFF      ABUF_HI(0)                 // aliases buf0 (all cp retired by then)
#define BIAS_OFF   205824                     // 32 floats
#define SMEM_DYN   (205824 + 128 + 1024)

// Parity-double-buffered bf16 hi/lo image of h (written once per element per step)
__device__ __align__(16) __nv_bfloat16 g_hhi[2][STEP_ELEMS];
__device__ __align__(16) __nv_bfloat16 g_hlo[2][STEP_ELEMS];
__device__ unsigned long long g_count;

__global__ void init_kernel() { g_count = 0ULL; }

__device__ __forceinline__ uint32_t smem_u32(const void* p) {
    uint32_t a;
    asm("{ .reg .u64 t; cvta.to.shared.u64 t, %1; cvt.u32.u64 %0, t; }" : "=r"(a) : "l"(p));
    return a;
}
#define CP_ASYNC16(dst_u32, gptr) \
    asm volatile("cp.async.cg.shared.global [%0], [%1], 16;" :: "r"(dst_u32), "l"(gptr))
#define CP_COMMIT() asm volatile("cp.async.commit_group;" ::: "memory")
#define CP_WAIT(N)  asm volatile("cp.async.wait_group %0;" :: "n"(N) : "memory")

__device__ __forceinline__ uint32_t bf16_rne_bits(float x) {
    uint32_t xb = __float_as_uint(x);
    return (xb + 0x7FFFu + ((xb >> 16) & 1u)) & 0xFFFF0000u;
}
// pack two fp32 -> bf16x2 (e0 low, e1 high)
__device__ __forceinline__ uint32_t pack2_bf16(float e0, float e1) {
    uint32_t r;
    asm("cvt.rn.bf16x2.f32 %0, %1, %2;" : "=r"(r) : "f"(e1), "f"(e0));
    return r;
}
__device__ __forceinline__ void stg_cg_v4(void* p, uint32_t x, uint32_t y, uint32_t z, uint32_t w) {
    asm volatile("st.global.cg.v4.b32 [%0], {%1,%2,%3,%4};" :: "l"(p), "r"(x), "r"(y), "r"(z), "r"(w));
}
__device__ __forceinline__ float fsigm(float x) { return __fdividef(1.0f, 1.0f + __expf(-x)); }
__device__ __forceinline__ float ftanh(float x) { return __fdividef(2.0f, 1.0f + __expf(-2.0f * x)) - 1.0f; }

// ---------------------------------------------------------------------------
// Step 0 (exact fp32): x = 0, h = enc[0, b, ENC_LEN-1, :]. Seeds bf16 scratch.
// ---------------------------------------------------------------------------
__global__ void gru_step0(const float* __restrict__ enc,
                          const float* __restrict__ W_hh,
                          const float* __restrict__ b_ih,
                          const float* __restrict__ b_hh,
                          float* __restrict__ out)
{
    __shared__ float h0s[H];
    __shared__ float gh[3 * H];

    const int b = blockIdx.x, tid = threadIdx.x;
    const float* src = enc + ((size_t)b * ENC_LEN + (ENC_LEN - 1)) * H;
    for (int i = tid; i < H; i += NTHREADS) h0s[i] = src[i];
    __syncthreads();

    const int warp = tid >> 5, lane = tid & 31;
    const float4* h4 = (const float4*)h0s;
    for (int row = warp; row < 3 * H; row += (NTHREADS / 32)) {
        const float4* wr = (const float4*)(W_hh + (size_t)row * H);
        float s = 0.0f;
        #pragma unroll 4
        for (int i = lane; i < H / 4; i += 32) {
            float4 w = wr[i]; float4 hv = h4[i];
            s = fmaf(w.x, hv.x, s); s = fmaf(w.y, hv.y, s);
            s = fmaf(w.z, hv.z, s); s = fmaf(w.w, hv.w, s);
        }
        #pragma unroll
        for (int o = 16; o > 0; o >>= 1) s += __shfl_xor_sync(0xffffffffu, s, o);
        if (lane == 0) gh[row] = s;
    }
    __syncthreads();

    for (int j = tid; j < H; j += NTHREADS) {
        float r = 1.0f / (1.0f + expf(-(b_ih[j] + gh[j] + b_hh[j])));
        float z = 1.0f / (1.0f + expf(-(b_ih[H + j] + gh[H + j] + b_hh[H + j])));
        float n = tanhf(b_ih[2*H + j] + r * (gh[2*H + j] + b_hh[2*H + j]));
        float ho = h0s[j];
        float res = n + z * (ho - n);
        out[(size_t)b * H + j] = res;
        uint32_t hb = bf16_rne_bits(res);
        g_hhi[0][(size_t)b * H + j] = __ushort_as_bfloat16((unsigned short)(hb >> 16));
        g_hlo[0][(size_t)b * H + j] = __float2bfloat16(res - __uint_as_float(hb));
    }
}

// ---------------------------------------------------------------------------
// Persistent wmma kernel: steps 1..1023.
// D[64, 32] = h_half[64, 512] x Wc[32, 512]^T via bf16 hi/lo 3-term wmma.
// All 4 K-chunks cp.async'd upfront (4 commit groups, progressive waits).
// 3 accumulator fragments (one per term) break the HMMA dependency chain.
// Wc rows (n = gate*8+jl): 0=r (Wih+Whh), 1=z (Wih+Whh), 2=a (Wih), 3=g (Whh).
//   h' = (1-z)*tanh(a + sig(r)*g) + z*h
// ---------------------------------------------------------------------------
__global__ void __launch_bounds__(NTHREADS, 1)
gru_persist(const float* __restrict__ W_ih,
            const float* __restrict__ W_hh,
            const float* __restrict__ b_ih,
            const float* __restrict__ b_hh,
            float* __restrict__ out)
{
    extern __shared__ char smem_raw[];
    char* smem = (char*)(((uintptr_t)smem_raw + 1023u) & ~(uintptr_t)1023u);

    const int tid = threadIdx.x;
    const int wid = tid >> 5;
    const int jc     = blockIdx.x >> 1;        // 0..63
    const int mhalf  = blockIdx.x & 1;         // 0..1
    const int jglob  = jc * JC;
    const int mb0    = mhalf * MROWS;

    __nv_bfloat16* w_hi = (__nv_bfloat16*)(smem + W_HI_OFF);
    __nv_bfloat16* w_lo = (__nv_bfloat16*)(smem + W_LO_OFF);
    float* bias_s = (float*)(smem + BIAS_OFF);
    float* d_s    = (float*)(smem + D_OFF);

    // ---- Prologue: combined weights -> bf16 hi/lo SMEM tiles (once)
    for (int idx = tid; idx < NB * H; idx += NTHREADS) {
        int r = idx >> 9, k = idx & (H - 1);
        int g = r >> 3, jl = r & 7;
        int j = jglob + jl;
        float c;
        if (g == 0)      c = W_ih[(size_t)j * H + k]           + W_hh[(size_t)j * H + k];
        else if (g == 1) c = W_ih[(size_t)(H + j) * H + k]     + W_hh[(size_t)(H + j) * H + k];
        else if (g == 2) c = W_ih[(size_t)(2*H + j) * H + k];
        else             c = W_hh[(size_t)(2*H + j) * H + k];
        uint32_t hb = bf16_rne_bits(c);
        w_hi[r * W_LD + k] = __ushort_as_bfloat16((unsigned short)(hb >> 16));
        w_lo[r * W_LD + k] = __float2bfloat16(c - __uint_as_float(hb));
    }
    if (tid < NB) {
        int g = tid >> 3, jl = tid & 7;
        int j = jglob + jl;
        float v;
        if (g == 0)      v = b_ih[j]        + b_hh[j];
        else if (g == 1) v = b_ih[H + j]    + b_hh[H + j];
        else if (g == 2) v = b_ih[2*H + j];
        else             v = b_hh[2*H + j];
        bias_s[tid] = v;
    }
    __syncthreads();

    const int ms = wid >> 1;               // 0..3 m-slice (16 rows)
    const int nt = wid & 1;                // 0..1 n-tile
    const int m0 = ms * 16;
    const int n0 = nt * 16;

    for (int t = 1; t < TSTEPS; ++t) {
        const int rpar = (t - 1) & 1;
        const int wpar = t & 1;
        const __nv_bfloat16* shi = g_hhi[rpar];
        const __nv_bfloat16* slo = g_hlo[rpar];

        // ---- prefetch h_old for epilogue (hidden under the whole mainloop)
        float4 hoa, hob;
        if (tid < MROWS) {
            const float* hop = out + (size_t)(t - 1) * STEP_ELEMS
                             + (size_t)(mb0 + tid) * H + jglob;
            hoa = __ldcg((const float4*)hop);
            hob = __ldcg((const float4*)(hop + 4));
        }

        // ---- issue ALL 4 chunk copies upfront (one commit group per chunk)
        #pragma unroll
        for (int kc = 0; kc < NKC; ++kc) {
            char* ahi = smem + ABUF_HI(kc);
            char* alo = smem + ABUF_LO(kc);
            const __nv_bfloat16* ghi = shi + (size_t)mb0 * H + kc * KCHUNK;
            const __nv_bfloat16* glo = slo + (size_t)mb0 * H + kc * KCHUNK;
            #pragma unroll
            for (int i = 0; i < 4; ++i) {
                int unit = tid + i * NTHREADS;      // 0..1023
                int row  = unit >> 4;
                int u    = unit & 15;
                uint32_t doff = (uint32_t)row * (A_LD * 2) + u * 16;
                size_t   soff = (size_t)row * H + u * 8;
                CP_ASYNC16(smem_u32(ahi + doff), ghi + soff);
                CP_ASYNC16(smem_u32(alo + doff), glo + soff);
            }
            CP_COMMIT();
        }

        // ---- 3 independent accumulator chains (one per split term)
        wmma::fragment<wmma::accumulator, 16, 16, 16, float> acc0, acc1, acc2;
        wmma::fill_fragment(acc0, 0.0f);
        wmma::fill_fragment(acc1, 0.0f);
        wmma::fill_fragment(acc2, 0.0f);

        #pragma unroll
        for (int kc = 0; kc < NKC; ++kc) {
            if      (kc == 0) { CP_WAIT(3); }
            else if (kc == 1) { CP_WAIT(2); }
            else if (kc == 2) { CP_WAIT(1); }
            else              { CP_WAIT(0); }
            __syncthreads();

            __nv_bfloat16* ahi = (__nv_bfloat16*)(smem + ABUF_HI(kc));
            __nv_bfloat16* alo = (__nv_bfloat16*)(smem + ABUF_LO(kc));

            #pragma unroll 2
            for (int ks = 0; ks < KCHUNK / 16; ++ks) {
                wmma::fragment<wmma::matrix_a, 16, 16, 16, __nv_bfloat16, wmma::row_major> a_hi, a_lo;
                wmma::load_matrix_sync(a_hi, ahi + m0 * A_LD + ks * 16, A_LD);
                wmma::load_matrix_sync(a_lo, alo + m0 * A_LD + ks * 16, A_LD);
                const int kg = kc * KCHUNK + ks * 16;
                wmma::fragment<wmma::matrix_b, 16, 16, 16, __nv_bfloat16, wmma::col_major> b_hi, b_lo;
                wmma::load_matrix_sync(b_hi, w_hi + n0 * W_LD + kg, W_LD);
                wmma::load_matrix_sync(b_lo, w_lo + n0 * W_LD + kg, W_LD);
                wmma::mma_sync(acc0, a_hi, b_hi, acc0);
                wmma::mma_sync(acc1, a_lo, b_hi, acc1);
                wmma::mma_sync(acc2, a_hi, b_lo, acc2);
            }
        }

        // merge the 3 term chains
        #pragma unroll
        for (int i = 0; i < acc0.num_elements; ++i)
            acc0.x[i] += acc1.x[i] + acc2.x[i];

        // ---- epilogue: D -> SMEM (aliases buf0; all cp.async retired)
        __syncthreads();
        wmma::store_matrix_sync(d_s + m0 * D_LD + n0, acc0, D_LD, wmma::mem_row_major);
        __syncthreads();

        if (tid < MROWS) {
            const int b = mb0 + tid;
            const float* drow = d_s + tid * D_LD;
            float ho[8] = { hoa.x, hoa.y, hoa.z, hoa.w, hob.x, hob.y, hob.z, hob.w };

            float res[8];
            uint32_t hi4[4], lo4[4];
            #pragma unroll
            for (int jl = 0; jl < 8; ++jl) {
                float r = fsigm(drow[jl]      + bias_s[jl]);
                float z = fsigm(drow[8 + jl]  + bias_s[8 + jl]);
                float a = drow[16 + jl] + bias_s[16 + jl];
                float g = drow[24 + jl] + bias_s[24 + jl];
                float n = ftanh(a + r * g);
                res[jl] = n + z * (ho[jl] - n);
            }
            #pragma unroll
            for (int p = 0; p < 4; ++p) {
                uint32_t h0b = bf16_rne_bits(res[2*p]);
                uint32_t h1b = bf16_rne_bits(res[2*p + 1]);
                hi4[p] = (h0b >> 16) | (h1b & 0xFFFF0000u);
                lo4[p] = pack2_bf16(res[2*p]     - __uint_as_float(h0b),
                                    res[2*p + 1] - __uint_as_float(h1b));
            }
            float* dst = out + (size_t)t * STEP_ELEMS + (size_t)b * H + jglob;
            __stcg((float4*)dst,       make_float4(res[0], res[1], res[2], res[3]));
            __stcg((float4*)(dst + 4), make_float4(res[4], res[5], res[6], res[7]));
            stg_cg_v4(&g_hhi[wpar][(size_t)b * H + jglob], hi4[0], hi4[1], hi4[2], hi4[3]);
            stg_cg_v4(&g_hlo[wpar][(size_t)b * H + jglob], lo4[0], lo4[1], lo4[2], lo4[3]);
        }

        // ---- grid barrier (release pattern: sync, then tid0 fence+arrive+poll)
        if (t + 1 < TSTEPS) {
            __syncthreads();
            if (tid == 0) {
                __threadfence();
                atomicAdd(&g_count, 1ULL);
                unsigned long long target = (unsigned long long)t * (unsigned long long)GRID;
                while (*(volatile unsigned long long*)&g_count < target) { }
            }
            __syncthreads();
        } else {
            __syncthreads();
        }
    }
}

// ---------------------------------------------------------------------------
// Harness entry. Inputs: enc f32[1,128,100,512], W_ih f32[1536,512],
// W_hh f32[1536,512], b_ih f32[1536], b_hh f32[1536], out_len i32.
// Output: f32[1024*128, 1, 512]
// ---------------------------------------------------------------------------
extern "C" void kernel_launch(void* const* d_in, const int* in_sizes, int n_in,
                              void* d_out, int out_size)
{
    const float* enc  = (const float*)d_in[0];
    const float* W_ih = (const float*)d_in[1];
    const float* W_hh = (const float*)d_in[2];
    const float* b_ih = (const float*)d_in[3];
    const float* b_hh = (const float*)d_in[4];
    float* out = (float*)d_out;

    cudaFuncSetAttribute(gru_persist, cudaFuncAttributeMaxDynamicSharedMemorySize, SMEM_DYN);

    init_kernel<<<1, 1>>>();
    gru_step0<<<BATCH, NTHREADS>>>(enc, W_hh, b_ih, b_hh, out);
    gru_persist<<<GRID, NTHREADS, SMEM_DYN>>>(W_ih, W_hh, b_ih, b_hh, out);
}

// round 14
// speedup vs baseline: 2.0055x; 1.0011x over previous
#include <cuda_runtime.h>
#include <cuda_bf16.h>
#include <mma.h>
#include <math.h>
#include <stdint.h>

using namespace nvcuda;

// Problem constants
#define H        512
#define BATCH    128
#define ENC_LEN  100
#define TSTEPS   1024
#define STEP_ELEMS (BATCH * H)

// Persistent geometry: 128 CTAs = 64 j-chunks x 2 batch-halves.
// Each CTA: M=64 batch rows, N=32 weight rows (4 gates x JC=8), K=512 (4 chunks).
// 512 threads = 16 warps = 4 m-slices x 2 n-tiles x 2 k-subgroups.
#define GRID     128
#define NTHREADS 512
#define S0THREADS 256
#define JC       8
#define NB       32
#define MROWS    64
#define KCHUNK   128
#define NKC      4

// SMEM element strides (all %8==0 for wmma ldm)
#define A_LD     136        // A chunk tile leading dim (bf16)
#define W_LD     520        // W tile leading dim (bf16)
#define D_LD     40         // D scratch leading dim (f32)

// SMEM byte offsets — 4 A buffers (all chunks in flight)
#define W_HI_OFF   0                          // 32 x 520 bf16 = 33280
#define W_LO_OFF   33280
#define ABUF_HI(b) (66560 + (b) * 34816)      // per buf: hi 64x136x2=17408 + lo
#define ABUF_LO(b) (ABUF_HI(b) + 17408)
#define D0_OFF     ABUF_HI(0)                 // aliases buf0 (dead after chunk 0)
#define D1_OFF     (D0_OFF + 10240)           // 64*40*4 = 10240 per buffer
#define BIAS_OFF   205824                     // 32 floats
#define SMEM_DYN   (205824 + 128 + 1024)

// Parity-double-buffered bf16 hi/lo image of h (written once per element per step)
__device__ __align__(16) __nv_bfloat16 g_hhi[2][STEP_ELEMS];
__device__ __align__(16) __nv_bfloat16 g_hlo[2][STEP_ELEMS];
// Two independent barrier counters (one per batch-half group), separate lines
__device__ __align__(128) unsigned long long g_cnt[32];

__global__ void init_kernel() { g_cnt[0] = 0ULL; g_cnt[16] = 0ULL; }

__device__ __forceinline__ uint32_t smem_u32(const void* p) {
    uint32_t a;
    asm("{ .reg .u64 t; cvta.to.shared.u64 t, %1; cvt.u32.u64 %0, t; }" : "=r"(a) : "l"(p));
    return a;
}
#define CP_ASYNC16(dst_u32, gptr) \
    asm volatile("cp.async.cg.shared.global [%0], [%1], 16;" :: "r"(dst_u32), "l"(gptr))
#define CP_COMMIT() asm volatile("cp.async.commit_group;" ::: "memory")
#define CP_WAIT(N)  asm volatile("cp.async.wait_group %0;" :: "n"(N) : "memory")

__device__ __forceinline__ uint32_t bf16_rne_bits(float x) {
    uint32_t xb = __float_as_uint(x);
    return (xb + 0x7FFFu + ((xb >> 16) & 1u)) & 0xFFFF0000u;
}
// pack two fp32 -> bf16x2 (e0 low, e1 high)
__device__ __forceinline__ uint32_t pack2_bf16(float e0, float e1) {
    uint32_t r;
    asm("cvt.rn.bf16x2.f32 %0, %1, %2;" : "=r"(r) : "f"(e1), "f"(e0));
    return r;
}
__device__ __forceinline__ void stg_cg_v2(void* p, uint32_t x, uint32_t y) {
    asm volatile("st.global.cg.v2.b32 [%0], {%1,%2};" :: "l"(p), "r"(x), "r"(y));
}
__device__ __forceinline__ float fsigm(float x) { return __fdividef(1.0f, 1.0f + __expf(-x)); }
__device__ __forceinline__ float ftanh(float x) { return __fdividef(2.0f, 1.0f + __expf(-2.0f * x)) - 1.0f; }

// ---------------------------------------------------------------------------
// Step 0 (exact fp32): x = 0, h = enc[0, b, ENC_LEN-1, :]. Seeds bf16 scratch.
// ---------------------------------------------------------------------------
__global__ void gru_step0(const float* __restrict__ enc,
                          const float* __restrict__ W_hh,
                          const float* __restrict__ b_ih,
                          const float* __restrict__ b_hh,
                          float* __restrict__ out)
{
    __shared__ float h0s[H];
    __shared__ float gh[3 * H];

    const int b = blockIdx.x, tid = threadIdx.x;
    const float* src = enc + ((size_t)b * ENC_LEN + (ENC_LEN - 1)) * H;
    for (int i = tid; i < H; i += S0THREADS) h0s[i] = src[i];
    __syncthreads();

    const int warp = tid >> 5, lane = tid & 31;
    const float4* h4 = (const float4*)h0s;
    for (int row = warp; row < 3 * H; row += (S0THREADS / 32)) {
        const float4* wr = (const float4*)(W_hh + (size_t)row * H);
        float s = 0.0f;
        #pragma unroll 4
        for (int i = lane; i < H / 4; i += 32) {
            float4 w = wr[i]; float4 hv = h4[i];
            s = fmaf(w.x, hv.x, s); s = fmaf(w.y, hv.y, s);
            s = fmaf(w.z, hv.z, s); s = fmaf(w.w, hv.w, s);
        }
        #pragma unroll
        for (int o = 16; o > 0; o >>= 1) s += __shfl_xor_sync(0xffffffffu, s, o);
        if (lane == 0) gh[row] = s;
    }
    __syncthreads();

    for (int j = tid; j < H; j += S0THREADS) {
        float r = 1.0f / (1.0f + expf(-(b_ih[j] + gh[j] + b_hh[j])));
        float z = 1.0f / (1.0f + expf(-(b_ih[H + j] + gh[H + j] + b_hh[H + j])));
        float n = tanhf(b_ih[2*H + j] + r * (gh[2*H + j] + b_hh[2*H + j]));
        float ho = h0s[j];
        float res = n + z * (ho - n);
        out[(size_t)b * H + j] = res;
        uint32_t hb = bf16_rne_bits(res);
        g_hhi[0][(size_t)b * H + j] = __ushort_as_bfloat16((unsigned short)(hb >> 16));
        g_hlo[0][(size_t)b * H + j] = __float2bfloat16(res - __uint_as_float(hb));
    }
}

// ---------------------------------------------------------------------------
// Persistent wmma kernel: steps 1..1023.
// D[64, 32] = h_half[64, 512] x Wc[32, 512]^T via bf16 hi/lo 3-term wmma.
// All 4 K-chunks cp.async'd upfront; each chunk processed by all 16 warps
// (2 k-subgroups of 4 k-steps each). Cross-ksub reduce via 2 D buffers.
// Two independent 64-CTA barrier groups (batch halves are closed systems).
// ---------------------------------------------------------------------------
__global__ void __launch_bounds__(NTHREADS, 1)
gru_persist(const float* __restrict__ W_ih,
            const float* __restrict__ W_hh,
            const float* __restrict__ b_ih,
            const float* __restrict__ b_hh,
            float* __restrict__ out)
{
    extern __shared__ char smem_raw[];
    char* smem = (char*)(((uintptr_t)smem_raw + 1023u) & ~(uintptr_t)1023u);

    const int tid = threadIdx.x;
    const int wid = tid >> 5;
    const int jc     = blockIdx.x >> 1;        // 0..63
    const int mhalf  = blockIdx.x & 1;         // 0..1 (barrier group)
    const int jglob  = jc * JC;
    const int mb0    = mhalf * MROWS;
    volatile unsigned long long* cnt = &g_cnt[mhalf * 16];

    __nv_bfloat16* w_hi = (__nv_bfloat16*)(smem + W_HI_OFF);
    __nv_bfloat16* w_lo = (__nv_bfloat16*)(smem + W_LO_OFF);
    float* bias_s = (float*)(smem + BIAS_OFF);
    float* d_s0   = (float*)(smem + D0_OFF);
    float* d_s1   = (float*)(smem + D1_OFF);

    // ---- Prologue: combined weights -> bf16 hi/lo SMEM tiles (once)
    for (int idx = tid; idx < NB * H; idx += NTHREADS) {
        int r = idx >> 9, k = idx & (H - 1);
        int g = r >> 3, jl = r & 7;
        int j = jglob + jl;
        float c;
        if (g == 0)      c = W_ih[(size_t)j * H + k]           + W_hh[(size_t)j * H + k];
        else if (g == 1) c = W_ih[(size_t)(H + j) * H + k]     + W_hh[(size_t)(H + j) * H + k];
        else if (g == 2) c = W_ih[(size_t)(2*H + j) * H + k];
        else             c = W_hh[(size_t)(2*H + j) * H + k];
        uint32_t hb = bf16_rne_bits(c);
        w_hi[r * W_LD + k] = __ushort_as_bfloat16((unsigned short)(hb >> 16));
        w_lo[r * W_LD + k] = __float2bfloat16(c - __uint_as_float(hb));
    }
    if (tid < NB) {
        int g = tid >> 3, jl = tid & 7;
        int j = jglob + jl;
        float v;
        if (g == 0)      v = b_ih[j]        + b_hh[j];
        else if (g == 1) v = b_ih[H + j]    + b_hh[H + j];
        else if (g == 2) v = b_ih[2*H + j];
        else             v = b_hh[2*H + j];
        bias_s[tid] = v;
    }
    __syncthreads();

    // warp tiling: 4 m-slices x 2 n-tiles x 2 k-subgroups
    const int ms   = wid >> 2;             // 0..3
    const int nt   = (wid >> 1) & 1;       // 0..1
    const int ksub = wid & 1;              // 0..1
    const int m0 = ms * 16;
    const int n0 = nt * 16;
    float* d_mine = ksub ? d_s1 : d_s0;

    // epilogue mapping (tid < 128): row = tid>>1, j-quad = (tid&1)*4
    const int erow = tid >> 1;
    const int ejb  = (tid & 1) * 4;

    for (int t = 1; t < TSTEPS; ++t) {
        const int rpar = (t - 1) & 1;
        const int wpar = t & 1;
        const __nv_bfloat16* shi = g_hhi[rpar];
        const __nv_bfloat16* slo = g_hlo[rpar];

        // ---- prefetch h_old for epilogue (hidden under the whole mainloop)
        float4 hov;
        if (tid < 2 * MROWS) {
            const float* hop = out + (size_t)(t - 1) * STEP_ELEMS
                             + (size_t)(mb0 + erow) * H + jglob + ejb;
            hov = __ldcg((const float4*)hop);
        }

        // ---- issue ALL 4 chunk copies upfront (one commit group per chunk)
        #pragma unroll
        for (int kc = 0; kc < NKC; ++kc) {
            char* ahi = smem + ABUF_HI(kc);
            char* alo = smem + ABUF_LO(kc);
            const __nv_bfloat16* ghi = shi + (size_t)mb0 * H + kc * KCHUNK;
            const __nv_bfloat16* glo = slo + (size_t)mb0 * H + kc * KCHUNK;
            #pragma unroll
            for (int i = 0; i < 2; ++i) {
                int unit = tid + i * NTHREADS;      // 0..1023
                int row  = unit >> 4;
                int u    = unit & 15;
                uint32_t doff = (uint32_t)row * (A_LD * 2) + u * 16;
                size_t   soff = (size_t)row * H + u * 8;
                CP_ASYNC16(smem_u32(ahi + doff), ghi + soff);
                CP_ASYNC16(smem_u32(alo + doff), glo + soff);
            }
            CP_COMMIT();
        }

        // ---- 3 independent accumulator chains (one per split term)
        wmma::fragment<wmma::accumulator, 16, 16, 16, float> acc0, acc1, acc2;
        wmma::fill_fragment(acc0, 0.0f);
        wmma::fill_fragment(acc1, 0.0f);
        wmma::fill_fragment(acc2, 0.0f);

        #pragma unroll
        for (int kc = 0; kc < NKC; ++kc) {
            if      (kc == 0) { CP_WAIT(3); }
            else if (kc == 1) { CP_WAIT(2); }
            else if (kc == 2) { CP_WAIT(1); }
            else              { CP_WAIT(0); }
            __syncthreads();

            __nv_bfloat16* ahi = (__nv_bfloat16*)(smem + ABUF_HI(kc));
            __nv_bfloat16* alo = (__nv_bfloat16*)(smem + ABUF_LO(kc));

            // this warp's 4 k-steps within the chunk
            #pragma unroll
            for (int s = 0; s < 4; ++s) {
                const int ks = ksub * 4 + s;
                wmma::fragment<wmma::matrix_a, 16, 16, 16, __nv_bfloat16, wmma::row_major> a_hi, a_lo;
                wmma::load_matrix_sync(a_hi, ahi + m0 * A_LD + ks * 16, A_LD);
                wmma::load_matrix_sync(a_lo, alo + m0 * A_LD + ks * 16, A_LD);
                const int kg = kc * KCHUNK + ks * 16;
                wmma::fragment<wmma::matrix_b, 16, 16, 16, __nv_bfloat16, wmma::col_major> b_hi, b_lo;
                wmma::load_matrix_sync(b_hi, w_hi + n0 * W_LD + kg, W_LD);
                wmma::load_matrix_sync(b_lo, w_lo + n0 * W_LD + kg, W_LD);
                wmma::mma_sync(acc0, a_hi, b_hi, acc0);
                wmma::mma_sync(acc1, a_lo, b_hi, acc1);
                wmma::mma_sync(acc2, a_hi, b_lo, acc2);
            }
        }

        // merge the 3 term chains; store this ksub's partial D
        #pragma unroll
        for (int i = 0; i < acc0.num_elements; ++i)
            acc0.x[i] += acc1.x[i] + acc2.x[i];
        // buf0 A data is dead after chunk 0 phase — safe to overwrite with D
        wmma::store_matrix_sync(d_mine + m0 * D_LD + n0, acc0, D_LD, wmma::mem_row_major);
        __syncthreads();

        // ---- epilogue: 128 threads, 4 elements each
        if (tid < 2 * MROWS) {
            const int b = mb0 + erow;
            const float* dr0 = d_s0 + erow * D_LD;
            const float* dr1 = d_s1 + erow * D_LD;
            float ho[4] = { hov.x, hov.y, hov.z, hov.w };

            float res[4];
            #pragma unroll
            for (int j = 0; j < 4; ++j) {
                int jl = ejb + j;
                float r = fsigm(dr0[jl]      + dr1[jl]      + bias_s[jl]);
                float z = fsigm(dr0[8 + jl]  + dr1[8 + jl]  + bias_s[8 + jl]);
                float a = dr0[16 + jl] + dr1[16 + jl] + bias_s[16 + jl];
                float g = dr0[24 + jl] + dr1[24 + jl] + bias_s[24 + jl];
                float n = ftanh(a + r * g);
                res[j] = n + z * (ho[j] - n);
            }
            uint32_t hi2[2], lo2[2];
            #pragma unroll
            for (int p = 0; p < 2; ++p) {
                uint32_t h0b = bf16_rne_bits(res[2*p]);
                uint32_t h1b = bf16_rne_bits(res[2*p + 1]);
                hi2[p] = (h0b >> 16) | (h1b & 0xFFFF0000u);
                lo2[p] = pack2_bf16(res[2*p]     - __uint_as_float(h0b),
                                    res[2*p + 1] - __uint_as_float(h1b));
            }
            size_t eoff = (size_t)b * H + jglob + ejb;
            float* dst = out + (size_t)t * STEP_ELEMS + eoff;
            __stcg((float4*)dst, make_float4(res[0], res[1], res[2], res[3]));
            stg_cg_v2(&g_hhi[wpar][eoff], hi2[0], hi2[1]);
            stg_cg_v2(&g_hlo[wpar][eoff], lo2[0], lo2[1]);
        }

        // ---- per-group grid barrier (64 CTAs; batch halves are independent)
        if (t + 1 < TSTEPS) {
            __syncthreads();
            if (tid == 0) {
                __threadfence();
                atomicAdd((unsigned long long*)cnt, 1ULL);
                unsigned long long target = (unsigned long long)t * 64ULL;
                while (*cnt < target) { }
            }
            __syncthreads();
        } else {
            __syncthreads();
        }
    }
}

// ---------------------------------------------------------------------------
// Harness entry. Inputs: enc f32[1,128,100,512], W_ih f32[1536,512],
// W_hh f32[1536,512], b_ih f32[1536], b_hh f32[1536], out_len i32.
// Output: f32[1024*128, 1, 512]
// ---------------------------------------------------------------------------
extern "C" void kernel_launch(void* const* d_in, const int* in_sizes, int n_in,
                              void* d_out, int out_size)
{
    const float* enc  = (const float*)d_in[0];
    const float* W_ih = (const float*)d_in[1];
    const float* W_hh = (const float*)d_in[2];
    const float* b_ih = (const float*)d_in[3];
    const float* b_hh = (const float*)d_in[4];
    float* out = (float*)d_out;

    cudaFuncSetAttribute(gru_persist, cudaFuncAttributeMaxDynamicSharedMemorySize, SMEM_DYN);

    init_kernel<<<1, 1>>>();
    gru_step0<<<BATCH, S0THREADS>>>(enc, W_hh, b_ih, b_hh, out);
    gru_persist<<<GRID, NTHREADS, SMEM_DYN>>>(W_ih, W_hh, b_ih, b_hh, out);
}